// round 1
// baseline (speedup 1.0000x reference)
#include <cuda_runtime.h>

#define NB 4
#define NQ 128
#define NK 1024
#define HD 256
#define DV 256

// Scratch (device globals — no allocation allowed)
__device__ float g_qp[NB * NQ * HD];      // 512 KB projected queries
__device__ float g_kp[NB * NK * HD];      // 4 MB projected keys
__device__ float g_scores[NB * NQ * NK];  // 2 MB raw scores

__device__ __forceinline__ float tanh_fast(float x) {
    float y;
    asm("tanh.approx.f32 %0, %1;" : "=f"(y) : "f"(x));
    return y;
}

// -------------------------------------------------------------------------
// Projection: out[r][h] = sum_d X[r][d] * W[h][d]
// Tiled 64x64, 256 threads, 4x4 per thread. which: 0 -> g_qp, 1 -> g_kp.
// -------------------------------------------------------------------------
__global__ __launch_bounds__(256) void proj_kernel(
    const float* __restrict__ X, const float* __restrict__ W, int which)
{
    __shared__ float Xs[64][17];
    __shared__ float Ws[64][17];

    float* out = which ? g_kp : g_qp;

    const int r0 = blockIdx.y * 64;
    const int h0 = blockIdx.x * 64;
    const int tid = threadIdx.x;
    const int tx = tid & 15;
    const int ty = tid >> 4;

    const int lr = tid >> 2;        // 0..63
    const int lc = (tid & 3) * 4;   // 0,4,8,12

    float acc[4][4] = {};

    for (int d0 = 0; d0 < HD; d0 += 16) {
        float4 xv = *(const float4*)&X[(r0 + lr) * HD + d0 + lc];
        float4 wt = *(const float4*)&W[(h0 + lr) * HD + d0 + lc];
        Xs[lr][lc + 0] = xv.x; Xs[lr][lc + 1] = xv.y;
        Xs[lr][lc + 2] = xv.z; Xs[lr][lc + 3] = xv.w;
        Ws[lr][lc + 0] = wt.x; Ws[lr][lc + 1] = wt.y;
        Ws[lr][lc + 2] = wt.z; Ws[lr][lc + 3] = wt.w;
        __syncthreads();

        #pragma unroll
        for (int dd = 0; dd < 16; dd++) {
            float xr[4], wr[4];
            #pragma unroll
            for (int i = 0; i < 4; i++) xr[i] = Xs[ty * 4 + i][dd];
            #pragma unroll
            for (int j = 0; j < 4; j++) wr[j] = Ws[tx * 4 + j][dd];
            #pragma unroll
            for (int i = 0; i < 4; i++)
                #pragma unroll
                for (int j = 0; j < 4; j++)
                    acc[i][j] += xr[i] * wr[j];
        }
        __syncthreads();
    }

    #pragma unroll
    for (int i = 0; i < 4; i++)
        #pragma unroll
        for (int j = 0; j < 4; j++)
            out[(r0 + ty * 4 + i) * HD + h0 + tx * 4 + j] = acc[i][j];
}

// -------------------------------------------------------------------------
// Scores: s[b,q,k] = sum_h wv[h] * tanh(qp[b,q,h] + kp[b,k,h])
// Block: 128 threads (4 warps), handles 8 queries x 128 keys.
// Lane owns h = lane*8 .. lane*8+7 (contiguous, float4-loadable).
// Warp handles 32 keys; per key: 64 tanh + warp butterfly reduce x8.
// Grid: (NK/128, NQ/8, B) = (8, 16, 4) = 512 blocks, ~1 wave at 4/SM.
// -------------------------------------------------------------------------
__global__ __launch_bounds__(128) void scores_kernel(const float* __restrict__ wv)
{
    const int b  = blockIdx.z;
    const int q0 = blockIdx.y * 8;
    const int k0 = blockIdx.x * 128;
    const int warp = threadIdx.x >> 5;
    const int lane = threadIdx.x & 31;
    const int hbase = lane * 8;

    // 8 query rows, 8 h-values each, in registers
    float qreg[8][8];
    const float* qbase = g_qp + (b * NQ + q0) * HD + hbase;
    #pragma unroll
    for (int j = 0; j < 8; j++) {
        float4 a = *(const float4*)(qbase + j * HD);
        float4 c = *(const float4*)(qbase + j * HD + 4);
        qreg[j][0] = a.x; qreg[j][1] = a.y; qreg[j][2] = a.z; qreg[j][3] = a.w;
        qreg[j][4] = c.x; qreg[j][5] = c.y; qreg[j][6] = c.z; qreg[j][7] = c.w;
    }

    float wr[8];
    {
        float4 a = *(const float4*)(wv + hbase);
        float4 c = *(const float4*)(wv + hbase + 4);
        wr[0] = a.x; wr[1] = a.y; wr[2] = a.z; wr[3] = a.w;
        wr[4] = c.x; wr[5] = c.y; wr[6] = c.z; wr[7] = c.w;
    }

    const float* kbase = g_kp + (size_t)b * NK * HD + hbase;

    for (int it = 0; it < 32; it++) {
        const int key = k0 + warp * 32 + it;
        const float* kp = kbase + key * HD;
        float4 ka = *(const float4*)kp;
        float4 kc = *(const float4*)(kp + 4);
        float kr[8] = {ka.x, ka.y, ka.z, ka.w, kc.x, kc.y, kc.z, kc.w};

        float acc[8];
        #pragma unroll
        for (int j = 0; j < 8; j++) {
            float s = 0.f;
            #pragma unroll
            for (int i = 0; i < 8; i++)
                s += wr[i] * tanh_fast(qreg[j][i] + kr[i]);
            acc[j] = s;
        }

        #pragma unroll
        for (int j = 0; j < 8; j++) {
            float v = acc[j];
            v += __shfl_xor_sync(0xFFFFFFFFu, v, 16);
            v += __shfl_xor_sync(0xFFFFFFFFu, v, 8);
            v += __shfl_xor_sync(0xFFFFFFFFu, v, 4);
            v += __shfl_xor_sync(0xFFFFFFFFu, v, 2);
            v += __shfl_xor_sync(0xFFFFFFFFu, v, 1);
            if (lane == 0)
                g_scores[(b * NQ + q0 + j) * NK + key] = v;
        }
    }
}

// -------------------------------------------------------------------------
// Fused masked softmax + AV.
// Block: 128 threads, handles 8 queries x 128 output dims (one v-half).
// Softmax normalized probs stored transposed in smem pt[k][j] so the AV
// inner loop reads them as two float4 broadcasts per key.
// Grid: (2, NQ/8, B) = (2, 16, 4) = 128 blocks.
// -------------------------------------------------------------------------
__global__ __launch_bounds__(128) void softmax_av_kernel(
    const float* __restrict__ V, const int* __restrict__ valid_lens,
    float* __restrict__ out)
{
    __shared__ float pt[NK][8];   // 32 KB
    __shared__ float red[4];

    const int b  = blockIdx.z;
    const int q0 = blockIdx.y * 8;
    const int vh = blockIdx.x;
    const int tid = threadIdx.x;
    const int warp = tid >> 5;
    const int lane = tid & 31;
    const int vlen = valid_lens[b];

    for (int j = 0; j < 8; j++) {
        const float* row = g_scores + (size_t)(b * NQ + q0 + j) * NK;
        float s[8];
        float mx = -1e30f;
        #pragma unroll
        for (int u = 0; u < 8; u++) {
            int k = tid + u * 128;
            float val = (k < vlen) ? row[k] : -1e6f;
            s[u] = val;
            mx = fmaxf(mx, val);
        }
        #pragma unroll
        for (int off = 16; off; off >>= 1)
            mx = fmaxf(mx, __shfl_xor_sync(0xFFFFFFFFu, mx, off));
        if (lane == 0) red[warp] = mx;
        __syncthreads();
        mx = fmaxf(fmaxf(red[0], red[1]), fmaxf(red[2], red[3]));
        __syncthreads();

        float e[8], sum = 0.f;
        #pragma unroll
        for (int u = 0; u < 8; u++) {
            e[u] = __expf(s[u] - mx);
            sum += e[u];
        }
        #pragma unroll
        for (int off = 16; off; off >>= 1)
            sum += __shfl_xor_sync(0xFFFFFFFFu, sum, off);
        if (lane == 0) red[warp] = sum;
        __syncthreads();
        sum = red[0] + red[1] + red[2] + red[3];
        float inv = 1.f / sum;
        #pragma unroll
        for (int u = 0; u < 8; u++)
            pt[tid + u * 128][j] = e[u] * inv;
        __syncthreads();
    }

    // AV: thread owns one output dim v, 8 query accumulators
    const int v = vh * 128 + tid;
    const float* Vb = V + (size_t)b * NK * DV + v;
    float acc[8] = {};
    #pragma unroll 4
    for (int k = 0; k < NK; k++) {
        float vv = Vb[(size_t)k * DV];
        float4 p0 = *(const float4*)&pt[k][0];
        float4 p1 = *(const float4*)&pt[k][4];
        acc[0] += p0.x * vv; acc[1] += p0.y * vv;
        acc[2] += p0.z * vv; acc[3] += p0.w * vv;
        acc[4] += p1.x * vv; acc[5] += p1.y * vv;
        acc[6] += p1.z * vv; acc[7] += p1.w * vv;
    }
    #pragma unroll
    for (int j = 0; j < 8; j++)
        out[(size_t)(b * NQ + q0 + j) * DV + v] = acc[j];
}

// -------------------------------------------------------------------------
extern "C" void kernel_launch(void* const* d_in, const int* in_sizes, int n_in,
                              void* d_out, int out_size)
{
    const float* queries = (const float*)d_in[0];
    const float* keys    = (const float*)d_in[1];
    const float* values  = (const float*)d_in[2];
    const int*   vlens   = (const int*)d_in[3];
    const float* Wq      = (const float*)d_in[4];
    const float* Wk      = (const float*)d_in[5];
    const float* wv      = (const float*)d_in[6];
    float* out = (float*)d_out;

    // q projection: 512 rows -> grid (4, 8)
    proj_kernel<<<dim3(4, 8), 256>>>(queries, Wq, 0);
    // k projection: 4096 rows -> grid (4, 64)
    proj_kernel<<<dim3(4, 64), 256>>>(keys, Wk, 1);
    // scores
    scores_kernel<<<dim3(8, 16, 4), 128>>>(wv);
    // softmax + AV
    softmax_av_kernel<<<dim3(2, 16, 4), 128>>>(values, vlens, out);
}

// round 2
// speedup vs baseline: 1.3558x; 1.3558x over previous
#include <cuda_runtime.h>

#define NB 4
#define NQ 128
#define NK 1024
#define HD 256
#define DV 256

// Scratch (device globals — no allocation allowed)
__device__ float g_qp[NB * NQ * HD];      // 512 KB projected queries
__device__ float g_kp[NB * NK * HD];      // 4 MB projected keys
__device__ float g_scores[NB * NQ * NK];  // 2 MB scores -> probs (in place)

__device__ __forceinline__ float tanh_fast(float x) {
    float y;
    asm("tanh.approx.f32 %0, %1;" : "=f"(y) : "f"(x));
    return y;
}

// -------------------------------------------------------------------------
// Projection: out[r][h] = sum_d X[r][d] * W[h][d]
// Tiled 64x64, 256 threads, 4x4 per thread. which: 0 -> g_qp, 1 -> g_kp.
// -------------------------------------------------------------------------
__global__ __launch_bounds__(256) void proj_kernel(
    const float* __restrict__ X, const float* __restrict__ W, int which)
{
    __shared__ float Xs[64][17];
    __shared__ float Ws[64][17];

    float* out = which ? g_kp : g_qp;

    const int r0 = blockIdx.y * 64;
    const int h0 = blockIdx.x * 64;
    const int tid = threadIdx.x;
    const int tx = tid & 15;
    const int ty = tid >> 4;

    const int lr = tid >> 2;        // 0..63
    const int lc = (tid & 3) * 4;   // 0,4,8,12

    float acc[4][4] = {};

    for (int d0 = 0; d0 < HD; d0 += 16) {
        float4 xv = *(const float4*)&X[(r0 + lr) * HD + d0 + lc];
        float4 wt = *(const float4*)&W[(h0 + lr) * HD + d0 + lc];
        Xs[lr][lc + 0] = xv.x; Xs[lr][lc + 1] = xv.y;
        Xs[lr][lc + 2] = xv.z; Xs[lr][lc + 3] = xv.w;
        Ws[lr][lc + 0] = wt.x; Ws[lr][lc + 1] = wt.y;
        Ws[lr][lc + 2] = wt.z; Ws[lr][lc + 3] = wt.w;
        __syncthreads();

        #pragma unroll
        for (int dd = 0; dd < 16; dd++) {
            float xr[4], wr[4];
            #pragma unroll
            for (int i = 0; i < 4; i++) xr[i] = Xs[ty * 4 + i][dd];
            #pragma unroll
            for (int j = 0; j < 4; j++) wr[j] = Ws[tx * 4 + j][dd];
            #pragma unroll
            for (int i = 0; i < 4; i++)
                #pragma unroll
                for (int j = 0; j < 4; j++)
                    acc[i][j] += xr[i] * wr[j];
        }
        __syncthreads();
    }

    #pragma unroll
    for (int i = 0; i < 4; i++)
        #pragma unroll
        for (int j = 0; j < 4; j++)
            out[(r0 + ty * 4 + i) * HD + h0 + tx * 4 + j] = acc[i][j];
}

// -------------------------------------------------------------------------
// Scores: s[b,q,k] = sum_h wv[h] * tanh(qp[b,q,h] + kp[b,k,h])
// Block: 128 threads (4 warps), 8 queries x 128 keys. Lane owns 8 h-values.
// Grid: (8, 16, 4) = 512 blocks.
// -------------------------------------------------------------------------
__global__ __launch_bounds__(128) void scores_kernel(const float* __restrict__ wv)
{
    const int b  = blockIdx.z;
    const int q0 = blockIdx.y * 8;
    const int k0 = blockIdx.x * 128;
    const int warp = threadIdx.x >> 5;
    const int lane = threadIdx.x & 31;
    const int hbase = lane * 8;

    float qreg[8][8];
    const float* qbase = g_qp + (b * NQ + q0) * HD + hbase;
    #pragma unroll
    for (int j = 0; j < 8; j++) {
        float4 a = *(const float4*)(qbase + j * HD);
        float4 c = *(const float4*)(qbase + j * HD + 4);
        qreg[j][0] = a.x; qreg[j][1] = a.y; qreg[j][2] = a.z; qreg[j][3] = a.w;
        qreg[j][4] = c.x; qreg[j][5] = c.y; qreg[j][6] = c.z; qreg[j][7] = c.w;
    }

    float wr[8];
    {
        float4 a = *(const float4*)(wv + hbase);
        float4 c = *(const float4*)(wv + hbase + 4);
        wr[0] = a.x; wr[1] = a.y; wr[2] = a.z; wr[3] = a.w;
        wr[4] = c.x; wr[5] = c.y; wr[6] = c.z; wr[7] = c.w;
    }

    const float* kbase = g_kp + (size_t)b * NK * HD + hbase;

    for (int it = 0; it < 32; it++) {
        const int key = k0 + warp * 32 + it;
        const float* kp = kbase + key * HD;
        float4 ka = *(const float4*)kp;
        float4 kc = *(const float4*)(kp + 4);
        float kr[8] = {ka.x, ka.y, ka.z, ka.w, kc.x, kc.y, kc.z, kc.w};

        float acc[8];
        #pragma unroll
        for (int j = 0; j < 8; j++) {
            float s = 0.f;
            #pragma unroll
            for (int i = 0; i < 8; i++)
                s += wr[i] * tanh_fast(qreg[j][i] + kr[i]);
            acc[j] = s;
        }

        #pragma unroll
        for (int j = 0; j < 8; j++) {
            float v = acc[j];
            v += __shfl_xor_sync(0xFFFFFFFFu, v, 16);
            v += __shfl_xor_sync(0xFFFFFFFFu, v, 8);
            v += __shfl_xor_sync(0xFFFFFFFFu, v, 4);
            v += __shfl_xor_sync(0xFFFFFFFFu, v, 2);
            v += __shfl_xor_sync(0xFFFFFFFFu, v, 1);
            if (lane == 0)
                g_scores[(b * NQ + q0 + j) * NK + key] = v;
        }
    }
}

// -------------------------------------------------------------------------
// Masked softmax over each 1024-long score row, in place.
// One 256-thread block per row; each thread owns 4 contiguous values.
// Grid: NB*NQ = 512 blocks.
// -------------------------------------------------------------------------
__global__ __launch_bounds__(256) void softmax_kernel(const int* __restrict__ valid_lens)
{
    __shared__ float red[8];

    const int row = blockIdx.x;             // 0..511
    const int b   = row >> 7;               // row / NQ
    const int tid = threadIdx.x;
    const int warp = tid >> 5;
    const int lane = tid & 31;
    const int vlen = valid_lens[b];

    float* rp = g_scores + (size_t)row * NK + tid * 4;

    float4 v = *(const float4*)rp;
    const int kb = tid * 4;
    if (kb + 0 >= vlen) v.x = -1e6f;
    if (kb + 1 >= vlen) v.y = -1e6f;
    if (kb + 2 >= vlen) v.z = -1e6f;
    if (kb + 3 >= vlen) v.w = -1e6f;

    float mx = fmaxf(fmaxf(v.x, v.y), fmaxf(v.z, v.w));
    #pragma unroll
    for (int off = 16; off; off >>= 1)
        mx = fmaxf(mx, __shfl_xor_sync(0xFFFFFFFFu, mx, off));
    if (lane == 0) red[warp] = mx;
    __syncthreads();
    if (warp == 0) {
        float m = red[lane & 7];
        #pragma unroll
        for (int off = 4; off; off >>= 1)
            m = fmaxf(m, __shfl_xor_sync(0xFFFFFFFFu, m, off));
        if (lane == 0) red[0] = m;
    }
    __syncthreads();
    mx = red[0];
    __syncthreads();

    float4 e;
    e.x = __expf(v.x - mx); e.y = __expf(v.y - mx);
    e.z = __expf(v.z - mx); e.w = __expf(v.w - mx);
    float sum = e.x + e.y + e.z + e.w;
    #pragma unroll
    for (int off = 16; off; off >>= 1)
        sum += __shfl_xor_sync(0xFFFFFFFFu, sum, off);
    if (lane == 0) red[warp] = sum;
    __syncthreads();
    if (warp == 0) {
        float s = red[lane & 7];
        #pragma unroll
        for (int off = 4; off; off >>= 1)
            s += __shfl_xor_sync(0xFFFFFFFFu, s, off);
        if (lane == 0) red[0] = s;
    }
    __syncthreads();
    const float inv = 1.0f / red[0];

    e.x *= inv; e.y *= inv; e.z *= inv; e.w *= inv;
    *(float4*)rp = e;
}

// -------------------------------------------------------------------------
// Zero the output (it is poisoned; AV kernel accumulates with atomics).
// -------------------------------------------------------------------------
__global__ __launch_bounds__(256) void zero_kernel(float* __restrict__ out)
{
    const int i = blockIdx.x * 256 + threadIdx.x;
    *(float4*)(out + (size_t)i * 4) = make_float4(0.f, 0.f, 0.f, 0.f);
}

// -------------------------------------------------------------------------
// AV GEMM with split-K: out[r][v] += sum_k P[r][k] * V[b][k][v]
// Tile: 64 rows x 64 vdims, K-chunk 256 per block (split-K = 4).
// 256 threads, 4x4 outputs/thread, atomicAdd epilogue.
// Grid: (DV/64=4, NB*NQ/64=8, KSPLIT=4) = 128 blocks.
// -------------------------------------------------------------------------
__global__ __launch_bounds__(256) void av_kernel(
    const float* __restrict__ V, float* __restrict__ out)
{
    __shared__ float Ps[64][17];
    __shared__ float Vs[16][68];

    const int v0 = blockIdx.x * 64;
    const int r0 = blockIdx.y * 64;          // global row (b*NQ + q)
    const int b  = r0 >> 7;                  // 64 | 128, so whole tile same b
    const int kz = blockIdx.z * 256;

    const int tid = threadIdx.x;
    const int tx = tid & 15;
    const int ty = tid >> 4;

    const int plr = tid >> 2;                // 0..63
    const int plc = (tid & 3) * 4;           // 0,4,8,12
    const int vlr = tid >> 4;                // 0..15
    const int vlc = (tid & 15) * 4;          // 0..60

    const float* Vb = V + (size_t)b * NK * DV;

    float acc[4][4] = {};

    for (int k0 = kz; k0 < kz + 256; k0 += 16) {
        float4 pv = *(const float4*)&g_scores[(size_t)(r0 + plr) * NK + k0 + plc];
        Ps[plr][plc + 0] = pv.x; Ps[plr][plc + 1] = pv.y;
        Ps[plr][plc + 2] = pv.z; Ps[plr][plc + 3] = pv.w;
        float4 vv = *(const float4*)&Vb[(size_t)(k0 + vlr) * DV + v0 + vlc];
        Vs[vlr][vlc + 0] = vv.x; Vs[vlr][vlc + 1] = vv.y;
        Vs[vlr][vlc + 2] = vv.z; Vs[vlr][vlc + 3] = vv.w;
        __syncthreads();

        #pragma unroll
        for (int dd = 0; dd < 16; dd++) {
            float pr[4], vr[4];
            #pragma unroll
            for (int i = 0; i < 4; i++) pr[i] = Ps[ty * 4 + i][dd];
            #pragma unroll
            for (int j = 0; j < 4; j++) vr[j] = Vs[dd][tx * 4 + j];
            #pragma unroll
            for (int i = 0; i < 4; i++)
                #pragma unroll
                for (int j = 0; j < 4; j++)
                    acc[i][j] += pr[i] * vr[j];
        }
        __syncthreads();
    }

    #pragma unroll
    for (int i = 0; i < 4; i++)
        #pragma unroll
        for (int j = 0; j < 4; j++)
            atomicAdd(&out[(size_t)(r0 + ty * 4 + i) * DV + v0 + tx * 4 + j],
                      acc[i][j]);
}

// -------------------------------------------------------------------------
extern "C" void kernel_launch(void* const* d_in, const int* in_sizes, int n_in,
                              void* d_out, int out_size)
{
    const float* queries = (const float*)d_in[0];
    const float* keys    = (const float*)d_in[1];
    const float* values  = (const float*)d_in[2];
    const int*   vlens   = (const int*)d_in[3];
    const float* Wq      = (const float*)d_in[4];
    const float* Wk      = (const float*)d_in[5];
    const float* wv      = (const float*)d_in[6];
    float* out = (float*)d_out;

    // q projection: 512 rows -> grid (4, 8)
    proj_kernel<<<dim3(4, 8), 256>>>(queries, Wq, 0);
    // k projection: 4096 rows -> grid (4, 64)
    proj_kernel<<<dim3(4, 64), 256>>>(keys, Wk, 1);
    // scores
    scores_kernel<<<dim3(8, 16, 4), 128>>>(wv);
    // masked softmax (in place on g_scores)
    softmax_kernel<<<512, 256>>>(vlens);
    // zero output for atomic accumulation (512*256 = 131072 floats)
    zero_kernel<<<128, 256>>>(out);
    // AV GEMM, split-K=4
    av_kernel<<<dim3(4, 8, 4), 256>>>(values, out);
}

// round 3
// speedup vs baseline: 1.4719x; 1.0856x over previous
#include <cuda_runtime.h>

#define NB 4
#define NQ 128
#define NK 1024
#define HD 256
#define DV 256

// Scratch (device globals — no allocation allowed)
__device__ float g_qp[NB * NQ * HD];      // 512 KB projected queries
__device__ float g_kp[NB * NK * HD];      // 4 MB projected keys
__device__ float g_scores[NB * NQ * NK];  // 2 MB scores -> probs (in place)

__device__ __forceinline__ float tanh_fast(float x) {
    float y;
    asm("tanh.approx.f32 %0, %1;" : "=f"(y) : "f"(x));
    return y;
}

#define FFMA2(d, a, b, c) \
    asm("fma.rn.f32x2 %0, %1, %2, %3;" : "=l"(d) : "l"(a), "l"(b), "l"(c))
#define PACK2(d, lo, hi) \
    asm("mov.b64 %0, {%1, %2};" : "=l"(d) : "f"(lo), "f"(hi))
#define UNPACK2(lo, hi, d) \
    asm("mov.b64 {%0, %1}, %2;" : "=f"(lo), "=f"(hi) : "l"(d))

// -------------------------------------------------------------------------
// Projection: out[r][h] = sum_d X[r][d] * W[h][d]
// Tiled 64x64, 256 threads, 4x4 per thread, packed f32x2 FFMA.
// Smem tiles stored depth-major so inner loads are contiguous float4.
// -------------------------------------------------------------------------
__global__ __launch_bounds__(256) void proj_kernel(
    const float* __restrict__ X, const float* __restrict__ W, int which)
{
    __shared__ float Xt[16][68];   // [depth][row]
    __shared__ float Wt[16][68];   // [depth][col]

    float* out = which ? g_kp : g_qp;

    const int r0 = blockIdx.y * 64;
    const int h0 = blockIdx.x * 64;
    const int tid = threadIdx.x;
    const int tx = tid & 15;
    const int ty = tid >> 4;

    const int lr = tid >> 2;        // 0..63
    const int lc = (tid & 3) * 4;   // 0,4,8,12

    unsigned long long acc2[4][2] = {};

    for (int d0 = 0; d0 < HD; d0 += 16) {
        float4 xv = *(const float4*)&X[(size_t)(r0 + lr) * HD + d0 + lc];
        float4 wt = *(const float4*)&W[(size_t)(h0 + lr) * HD + d0 + lc];
        Xt[lc + 0][lr] = xv.x; Xt[lc + 1][lr] = xv.y;
        Xt[lc + 2][lr] = xv.z; Xt[lc + 3][lr] = xv.w;
        Wt[lc + 0][lr] = wt.x; Wt[lc + 1][lr] = wt.y;
        Wt[lc + 2][lr] = wt.z; Wt[lc + 3][lr] = wt.w;
        __syncthreads();

        #pragma unroll
        for (int dd = 0; dd < 16; dd++) {
            float4 xr = *(const float4*)&Xt[dd][ty * 4];
            float4 wr = *(const float4*)&Wt[dd][tx * 4];
            unsigned long long wp0, wp1;
            PACK2(wp0, wr.x, wr.y);
            PACK2(wp1, wr.z, wr.w);
            float xa[4] = {xr.x, xr.y, xr.z, xr.w};
            #pragma unroll
            for (int i = 0; i < 4; i++) {
                unsigned long long xb;
                PACK2(xb, xa[i], xa[i]);
                FFMA2(acc2[i][0], xb, wp0, acc2[i][0]);
                FFMA2(acc2[i][1], xb, wp1, acc2[i][1]);
            }
        }
        __syncthreads();
    }

    #pragma unroll
    for (int i = 0; i < 4; i++) {
        float o0, o1, o2, o3;
        UNPACK2(o0, o1, acc2[i][0]);
        UNPACK2(o2, o3, acc2[i][1]);
        *(float4*)&out[(size_t)(r0 + ty * 4 + i) * HD + h0 + tx * 4] =
            make_float4(o0, o1, o2, o3);
    }
}

// -------------------------------------------------------------------------
// Scores: s[b,q,k] = sum_h wv[h] * tanh(qp[b,q,h] + kp[b,k,h])
// Only keys k < valid_len[b] are computed (rest masked in softmax anyway).
// Block: 128 threads (4 warps), 8 queries x 128 keys. Lane owns 8 h-values.
// K-row register double-buffer hides L2 latency under MUFU work.
// Grid: (8, 16, 4) = 512 blocks.
// -------------------------------------------------------------------------
__global__ __launch_bounds__(128) void scores_kernel(
    const float* __restrict__ wv, const int* __restrict__ valid_lens)
{
    const int b  = blockIdx.z;
    const int q0 = blockIdx.y * 8;
    const int k0 = blockIdx.x * 128;
    const int warp = threadIdx.x >> 5;
    const int lane = threadIdx.x & 31;
    const int hbase = lane * 8;

    const int vlen = valid_lens[b];
    const int kw0 = k0 + warp * 32;
    int nit = vlen - kw0;
    if (nit <= 0) return;          // whole strip masked
    if (nit > 32) nit = 32;

    float qreg[8][8];
    const float* qbase = g_qp + (size_t)(b * NQ + q0) * HD + hbase;
    #pragma unroll
    for (int j = 0; j < 8; j++) {
        float4 a = *(const float4*)(qbase + j * HD);
        float4 c = *(const float4*)(qbase + j * HD + 4);
        qreg[j][0] = a.x; qreg[j][1] = a.y; qreg[j][2] = a.z; qreg[j][3] = a.w;
        qreg[j][4] = c.x; qreg[j][5] = c.y; qreg[j][6] = c.z; qreg[j][7] = c.w;
    }

    float wr[8];
    {
        float4 a = *(const float4*)(wv + hbase);
        float4 c = *(const float4*)(wv + hbase + 4);
        wr[0] = a.x; wr[1] = a.y; wr[2] = a.z; wr[3] = a.w;
        wr[4] = c.x; wr[5] = c.y; wr[6] = c.z; wr[7] = c.w;
    }

    const float* kbase = g_kp + (size_t)b * NK * HD + hbase;

    float4 ka = *(const float4*)(kbase + (size_t)kw0 * HD);
    float4 kc = *(const float4*)(kbase + (size_t)kw0 * HD + 4);

    for (int it = 0; it < nit; it++) {
        float4 na, nc;
        if (it + 1 < nit) {
            const float* np = kbase + (size_t)(kw0 + it + 1) * HD;
            na = *(const float4*)np;
            nc = *(const float4*)(np + 4);
        }

        float kr[8] = {ka.x, ka.y, ka.z, ka.w, kc.x, kc.y, kc.z, kc.w};

        float acc[8];
        #pragma unroll
        for (int j = 0; j < 8; j++) {
            float s = 0.f;
            #pragma unroll
            for (int i = 0; i < 8; i++)
                s += wr[i] * tanh_fast(qreg[j][i] + kr[i]);
            acc[j] = s;
        }

        #pragma unroll
        for (int j = 0; j < 8; j++) {
            float v = acc[j];
            v += __shfl_xor_sync(0xFFFFFFFFu, v, 16);
            v += __shfl_xor_sync(0xFFFFFFFFu, v, 8);
            v += __shfl_xor_sync(0xFFFFFFFFu, v, 4);
            v += __shfl_xor_sync(0xFFFFFFFFu, v, 2);
            v += __shfl_xor_sync(0xFFFFFFFFu, v, 1);
            if (lane == 0)
                g_scores[(size_t)(b * NQ + q0 + j) * NK + kw0 + it] = v;
        }

        ka = na; kc = nc;
    }
}

// -------------------------------------------------------------------------
// Masked softmax over each 1024-long score row, in place.
// One 256-thread block per row; each thread owns 4 contiguous values.
// Grid: NB*NQ = 512 blocks.
// -------------------------------------------------------------------------
__global__ __launch_bounds__(256) void softmax_kernel(const int* __restrict__ valid_lens)
{
    __shared__ float red[8];

    const int row = blockIdx.x;             // 0..511
    const int b   = row >> 7;               // row / NQ
    const int tid = threadIdx.x;
    const int warp = tid >> 5;
    const int lane = tid & 31;
    const int vlen = valid_lens[b];

    float* rp = g_scores + (size_t)row * NK + tid * 4;

    float4 v = *(const float4*)rp;
    const int kb = tid * 4;
    if (kb + 0 >= vlen) v.x = -1e6f;
    if (kb + 1 >= vlen) v.y = -1e6f;
    if (kb + 2 >= vlen) v.z = -1e6f;
    if (kb + 3 >= vlen) v.w = -1e6f;

    float mx = fmaxf(fmaxf(v.x, v.y), fmaxf(v.z, v.w));
    #pragma unroll
    for (int off = 16; off; off >>= 1)
        mx = fmaxf(mx, __shfl_xor_sync(0xFFFFFFFFu, mx, off));
    if (lane == 0) red[warp] = mx;
    __syncthreads();
    if (warp == 0) {
        float m = red[lane & 7];
        #pragma unroll
        for (int off = 4; off; off >>= 1)
            m = fmaxf(m, __shfl_xor_sync(0xFFFFFFFFu, m, off));
        if (lane == 0) red[0] = m;
    }
    __syncthreads();
    mx = red[0];
    __syncthreads();

    float4 e;
    e.x = __expf(v.x - mx); e.y = __expf(v.y - mx);
    e.z = __expf(v.z - mx); e.w = __expf(v.w - mx);
    float sum = e.x + e.y + e.z + e.w;
    #pragma unroll
    for (int off = 16; off; off >>= 1)
        sum += __shfl_xor_sync(0xFFFFFFFFu, sum, off);
    if (lane == 0) red[warp] = sum;
    __syncthreads();
    if (warp == 0) {
        float s = red[lane & 7];
        #pragma unroll
        for (int off = 4; off; off >>= 1)
            s += __shfl_xor_sync(0xFFFFFFFFu, s, off);
        if (lane == 0) red[0] = s;
    }
    __syncthreads();
    const float inv = 1.0f / red[0];

    e.x *= inv; e.y *= inv; e.z *= inv; e.w *= inv;
    *(float4*)rp = e;
}

// -------------------------------------------------------------------------
// Zero the output (poisoned; AV kernel accumulates with atomics).
// -------------------------------------------------------------------------
__global__ __launch_bounds__(256) void zero_kernel(float* __restrict__ out)
{
    const int i = blockIdx.x * 256 + threadIdx.x;
    *(float4*)(out + (size_t)i * 4) = make_float4(0.f, 0.f, 0.f, 0.f);
}

// -------------------------------------------------------------------------
// AV GEMM with split-K: out[r][v] += sum_k P[r][k] * V[b][k][v]
// Tile: 64 rows x 64 vdims, K-chunk 256 per block (split-K = 4).
// Chunks entirely beyond valid_len are skipped (their probs are exactly 0).
// Grid: (DV/64=4, NB*NQ/64=8, KSPLIT=4) = 128 blocks.
// -------------------------------------------------------------------------
__global__ __launch_bounds__(256) void av_kernel(
    const float* __restrict__ V, const int* __restrict__ valid_lens,
    float* __restrict__ out)
{
    __shared__ float Ps[64][17];
    __shared__ float Vs[16][68];

    const int v0 = blockIdx.x * 64;
    const int r0 = blockIdx.y * 64;          // global row (b*NQ + q)
    const int b  = r0 >> 7;
    const int kz = blockIdx.z * 256;

    if (kz >= valid_lens[b]) return;         // probs are exactly zero here

    const int tid = threadIdx.x;
    const int tx = tid & 15;
    const int ty = tid >> 4;

    const int plr = tid >> 2;                // 0..63
    const int plc = (tid & 3) * 4;           // 0,4,8,12
    const int vlr = tid >> 4;                // 0..15
    const int vlc = (tid & 15) * 4;          // 0..60

    const float* Vb = V + (size_t)b * NK * DV;

    float acc[4][4] = {};

    for (int k0 = kz; k0 < kz + 256; k0 += 16) {
        float4 pv = *(const float4*)&g_scores[(size_t)(r0 + plr) * NK + k0 + plc];
        Ps[plr][plc + 0] = pv.x; Ps[plr][plc + 1] = pv.y;
        Ps[plr][plc + 2] = pv.z; Ps[plr][plc + 3] = pv.w;
        float4 vv = *(const float4*)&Vb[(size_t)(k0 + vlr) * DV + v0 + vlc];
        Vs[vlr][vlc + 0] = vv.x; Vs[vlr][vlc + 1] = vv.y;
        Vs[vlr][vlc + 2] = vv.z; Vs[vlr][vlc + 3] = vv.w;
        __syncthreads();

        #pragma unroll
        for (int dd = 0; dd < 16; dd++) {
            float pr[4], vr[4];
            #pragma unroll
            for (int i = 0; i < 4; i++) pr[i] = Ps[ty * 4 + i][dd];
            #pragma unroll
            for (int j = 0; j < 4; j++) vr[j] = Vs[dd][tx * 4 + j];
            #pragma unroll
            for (int i = 0; i < 4; i++)
                #pragma unroll
                for (int j = 0; j < 4; j++)
                    acc[i][j] += pr[i] * vr[j];
        }
        __syncthreads();
    }

    #pragma unroll
    for (int i = 0; i < 4; i++)
        #pragma unroll
        for (int j = 0; j < 4; j++)
            atomicAdd(&out[(size_t)(r0 + ty * 4 + i) * DV + v0 + tx * 4 + j],
                      acc[i][j]);
}

// -------------------------------------------------------------------------
extern "C" void kernel_launch(void* const* d_in, const int* in_sizes, int n_in,
                              void* d_out, int out_size)
{
    const float* queries = (const float*)d_in[0];
    const float* keys    = (const float*)d_in[1];
    const float* values  = (const float*)d_in[2];
    const int*   vlens   = (const int*)d_in[3];
    const float* Wq      = (const float*)d_in[4];
    const float* Wk      = (const float*)d_in[5];
    const float* wv      = (const float*)d_in[6];
    float* out = (float*)d_out;

    // q projection: 512 rows -> grid (4, 8)
    proj_kernel<<<dim3(4, 8), 256>>>(queries, Wq, 0);
    // k projection: 4096 rows -> grid (4, 64)
    proj_kernel<<<dim3(4, 64), 256>>>(keys, Wk, 1);
    // scores (only k < valid_len computed)
    scores_kernel<<<dim3(8, 16, 4), 128>>>(wv, vlens);
    // masked softmax (in place on g_scores)
    softmax_kernel<<<512, 256>>>(vlens);
    // zero output for atomic accumulation
    zero_kernel<<<128, 256>>>(out);
    // AV GEMM, split-K=4, dead chunks skipped
    av_kernel<<<dim3(4, 8, 4), 256>>>(values, vlens, out);
}